// round 16
// baseline (speedup 1.0000x reference)
#include <cuda_runtime.h>
#include <cuda_bf16.h>
#include <math.h>
#include <stdint.h>

#define L 2048
#define DM 1024
#define NH 16
#define HD 64

// ---------------- Scratch (device globals — no allocation allowed) ----------
__device__ __align__(16) float g_part[64 * DM];
__device__ __align__(16) float g_Vsuf[64 * DM];
__device__ __align__(16) unsigned short g_Aah[(size_t)NH * L * L];  // A bf16 hi
__device__ __align__(16) unsigned short g_Aal[(size_t)NH * L * L];  // A bf16 lo
__device__ __align__(16) unsigned short g_Xhi[L * DM];
__device__ __align__(16) unsigned short g_Xlo[L * DM];
__device__ __align__(16) unsigned short g_Yhi[L * DM];
__device__ __align__(16) unsigned short g_Ylo[L * DM];
__device__ __align__(16) unsigned short g_Qhi[L * DM];
__device__ __align__(16) unsigned short g_Qlo[L * DM];
__device__ __align__(16) unsigned short g_Khi[L * DM];
__device__ __align__(16) unsigned short g_Klo[L * DM];
__device__ __align__(16) unsigned short g_Vhi[L * DM];
__device__ __align__(16) unsigned short g_Vlo[L * DM];
__device__ __align__(16) unsigned short g_Wthi[4 * DM * DM];  // W^T [n][k]
__device__ __align__(16) unsigned short g_Wtlo[4 * DM * DM];

// -log2(500)/64
#define ROPE_LOG2C 0.14009037944784838

__device__ __forceinline__ uint32_t smem_u32(const void* p) {
    uint32_t a;
    asm("{ .reg .u64 t; cvta.to.shared.u64 t, %1; cvt.u32.u64 %0, t; }" : "=r"(a) : "l"(p));
    return a;
}
__device__ __forceinline__ void cp16(uint32_t saddr, const void* gaddr) {
    asm volatile("cp.async.cg.shared.global [%0], [%1], 16;" :: "r"(saddr), "l"(gaddr));
}
#define CP_COMMIT() asm volatile("cp.async.commit_group;" ::: "memory")
#define CP_WAIT(n) asm volatile("cp.async.wait_group %0;" :: "n"(n) : "memory")

__device__ __forceinline__ void ldmx4(uint32_t addr, uint32_t& r0, uint32_t& r1,
                                      uint32_t& r2, uint32_t& r3) {
    asm volatile("ldmatrix.sync.aligned.m8n8.x4.shared.b16 {%0,%1,%2,%3}, [%4];"
                 : "=r"(r0), "=r"(r1), "=r"(r2), "=r"(r3) : "r"(addr));
}
__device__ __forceinline__ void ldmx4t(uint32_t addr, uint32_t& r0, uint32_t& r1,
                                       uint32_t& r2, uint32_t& r3) {
    asm volatile("ldmatrix.sync.aligned.m8n8.x4.trans.shared.b16 {%0,%1,%2,%3}, [%4];"
                 : "=r"(r0), "=r"(r1), "=r"(r2), "=r"(r3) : "r"(addr));
}
__device__ __forceinline__ void mma_bf16(float* c, uint32_t a0, uint32_t a1, uint32_t a2,
                                         uint32_t a3, uint32_t b0, uint32_t b1) {
    asm volatile(
        "mma.sync.aligned.m16n8k16.row.col.f32.bf16.bf16.f32 "
        "{%0,%1,%2,%3}, {%4,%5,%6,%7}, {%8,%9}, {%0,%1,%2,%3};"
        : "+f"(c[0]), "+f"(c[1]), "+f"(c[2]), "+f"(c[3])
        : "r"(a0), "r"(a1), "r"(a2), "r"(a3), "r"(b0), "r"(b1));
}

__device__ __forceinline__ unsigned short f2bf(float v) {
    __nv_bfloat16 b = __float2bfloat16(v);
    return *(unsigned short*)&b;
}
__device__ __forceinline__ float bf2f(unsigned short u) {
    __nv_bfloat16 b = *(__nv_bfloat16*)&u;
    return __bfloat162float(b);
}

// ---------------- Prep kernels ----------------------------------------------
__global__ __launch_bounds__(256) void xsplit(const float* __restrict__ X,
                                              unsigned short* __restrict__ hi,
                                              unsigned short* __restrict__ lo) {
    size_t i = ((size_t)blockIdx.x * 256 + threadIdx.x) * 4;
    float4 v = *(const float4*)(X + i);
    unsigned short h0 = f2bf(v.x), h1 = f2bf(v.y), h2 = f2bf(v.z), h3 = f2bf(v.w);
    unsigned short l0 = f2bf(v.x - bf2f(h0)), l1 = f2bf(v.y - bf2f(h1));
    unsigned short l2 = f2bf(v.z - bf2f(h2)), l3 = f2bf(v.w - bf2f(h3));
    *(uint2*)(hi + i) = make_uint2((uint32_t)h0 | ((uint32_t)h1 << 16),
                                   (uint32_t)h2 | ((uint32_t)h3 << 16));
    *(uint2*)(lo + i) = make_uint2((uint32_t)l0 | ((uint32_t)l1 << 16),
                                   (uint32_t)l2 | ((uint32_t)l3 << 16));
}

__global__ __launch_bounds__(256) void wsplit4(const float* __restrict__ W0,
                                               const float* __restrict__ W1,
                                               const float* __restrict__ W2,
                                               const float* __restrict__ W3) {
    __shared__ float s[32][33];
    const int z = blockIdx.z;
    const float* W = (z == 0) ? W0 : (z == 1) ? W1 : (z == 2) ? W2 : W3;
    unsigned short* hi = g_Wthi + (size_t)z * DM * DM;
    unsigned short* lo = g_Wtlo + (size_t)z * DM * DM;
    int n0 = blockIdx.x * 32, k0 = blockIdx.y * 32;
    int tx = threadIdx.x & 31, ty = threadIdx.x >> 5;
#pragma unroll
    for (int d = 0; d < 4; d++) {
        int i = ty * 4 + d;
        s[i][tx] = W[(size_t)(k0 + i) * DM + n0 + tx];
    }
    __syncthreads();
#pragma unroll
    for (int d = 0; d < 4; d++) {
        int i = ty * 4 + d;
        float v = s[tx][i];
        unsigned short h = f2bf(v);
        unsigned short l = f2bf(v - bf2f(h));
        hi[(size_t)(n0 + i) * DM + k0 + tx] = h;
        lo[(size_t)(n0 + i) * DM + k0 + tx] = l;
    }
}

// ---------------- HMMA GEMM body: paired-B ldmatrix.x4 -----------------------
#define OF_AH 0
#define OF_AL 8192
#define OF_BH 16384
#define OF_BL 32768
#define STG 49152
#define MM_SMEM (2 * STG)

__device__ __forceinline__ void mm_body(uint32_t smb, char* smm,
                                        const unsigned short* __restrict__ Ahi,
                                        const unsigned short* __restrict__ Alo,
                                        const unsigned short* __restrict__ Bhi,
                                        const unsigned short* __restrict__ Blo,
                                        float* __restrict__ Cf,
                                        unsigned short* __restrict__ Chi,
                                        unsigned short* __restrict__ Clo,
                                        int doRope, int m0, int n0) {
    const int tid = threadIdx.x;
    const int wid = tid >> 5, lid = tid & 31;
    const int wm = wid & 1, wn = wid >> 1;

    float acc[2][4][4] = {};

    const int lrow0 = tid >> 3, lch = tid & 7;
    const uint32_t lsw0 = (uint32_t)(lrow0 * 128 + ((lch * 16) ^ ((lrow0 & 7) << 4)));
    const uint32_t xorv = (uint32_t)((lid & 7) << 4);
    const uint32_t aRow = (uint32_t)((wm * 32 + (lid & 15)) * 128);
    // paired-B lane map: groups of 8 lanes cover rows j*8 / j*8+8 of the pair
    const uint32_t bRow = (uint32_t)((wn * 32 + ((lid >> 4) << 3) + (lid & 7)) * 128);
    const uint32_t aChBase = (uint32_t)((lid >> 4) << 4);
    const uint32_t bChBase = (uint32_t)(((lid >> 3) & 1) << 4);

#define LOAD_STAGE(k0c, stg) do {                                                  \
        uint32_t sb = smb + (stg)*STG;                                             \
        _Pragma("unroll")                                                          \
        for (int it = 0; it < 2; it++) {                                           \
            int row = lrow0 + it * 32;                                             \
            uint32_t so = lsw0 + it * 4096;                                        \
            size_t ga = (size_t)(m0 + row) * DM + (k0c) + lch * 8;                 \
            cp16(sb + OF_AH + so, Ahi + ga);                                       \
            cp16(sb + OF_AL + so, Alo + ga);                                       \
        }                                                                          \
        _Pragma("unroll")                                                          \
        for (int it = 0; it < 4; it++) {                                           \
            int row = lrow0 + it * 32;                                             \
            uint32_t so = lsw0 + it * 4096;                                        \
            size_t gb = (size_t)(n0 + row) * DM + (k0c) + lch * 8;                 \
            cp16(sb + OF_BH + so, Bhi + gb);                                       \
            cp16(sb + OF_BL + so, Blo + gb);                                       \
        }                                                                          \
        CP_COMMIT();                                                               \
    } while (0)

    LOAD_STAGE(0, 0);

    for (int c = 0; c < 16; c++) {
        if (c + 1 < 16) {
            LOAD_STAGE((c + 1) * 64, (c + 1) & 1);
            CP_WAIT(1);
        } else {
            CP_WAIT(0);
        }
        __syncthreads();

        const uint32_t st = smb + (c & 1) * STG;
        const uint32_t baseAh = st + OF_AH + aRow;
        const uint32_t baseAl = st + OF_AL + aRow;
        const uint32_t baseBh = st + OF_BH + bRow;
        const uint32_t baseBl = st + OF_BL + bRow;

#pragma unroll
        for (int ks = 0; ks < 4; ks++) {
            const uint32_t aCh = (uint32_t)(ks * 32 + aChBase) ^ xorv;
            const uint32_t bCh = (uint32_t)(ks * 32 + bChBase) ^ xorv;
            uint32_t bh[4][2], bl[4][2];
            // one x4 fetches two n8k16 B-fragments (rows j*8 and j*8+8)
            ldmx4(baseBh + bCh, bh[0][0], bh[0][1], bh[1][0], bh[1][1]);
            ldmx4(baseBh + 2048 + bCh, bh[2][0], bh[2][1], bh[3][0], bh[3][1]);
            ldmx4(baseBl + bCh, bl[0][0], bl[0][1], bl[1][0], bl[1][1]);
            ldmx4(baseBl + 2048 + bCh, bl[2][0], bl[2][1], bl[3][0], bl[3][1]);
#pragma unroll
            for (int i = 0; i < 2; i++) {
                uint32_t ah0, ah1, ah2, ah3, al0, al1, al2, al3;
                ldmx4(baseAh + i * 2048 + aCh, ah0, ah1, ah2, ah3);
                ldmx4(baseAl + i * 2048 + aCh, al0, al1, al2, al3);
#pragma unroll
                for (int j = 0; j < 4; j++) {
                    mma_bf16(acc[i][j], ah0, ah1, ah2, ah3, bh[j][0], bh[j][1]);
                    mma_bf16(acc[i][j], ah0, ah1, ah2, ah3, bl[j][0], bl[j][1]);
                    mma_bf16(acc[i][j], al0, al1, al2, al3, bh[j][0], bh[j][1]);
                }
            }
        }
        __syncthreads();
    }

    const int quad = lid & 3, trow = lid >> 2;
#pragma unroll
    for (int i = 0; i < 2; i++) {
        int mA = m0 + wm * 32 + i * 16 + trow;
#pragma unroll
        for (int j = 0; j < 4; j++) {
            int n = n0 + wn * 32 + j * 8 + quad * 2;
            float e0 = acc[i][j][0], o0 = acc[i][j][1];
            float e1 = acc[i][j][2], o1 = acc[i][j][3];
            if (doRope) {
                int t = n & 63;
                float fr = (float)exp2(-(double)t * ROPE_LOG2C);
                float s, c;
                sincosf((float)mA * fr, &s, &c);
                float te = e0;
                e0 = te * c - o0 * s;
                o0 = te * s + o0 * c;
                sincosf((float)(mA + 8) * fr, &s, &c);
                te = e1;
                e1 = te * c - o1 * s;
                o1 = te * s + o1 * c;
            }
            size_t p0 = (size_t)mA * DM + n, p1 = (size_t)(mA + 8) * DM + n;
            if (Cf) {
                *(float2*)(Cf + p0) = make_float2(e0, o0);
                *(float2*)(Cf + p1) = make_float2(e1, o1);
            }
            if (Chi) {
                unsigned short he0 = f2bf(e0), ho0 = f2bf(o0);
                unsigned short he1 = f2bf(e1), ho1 = f2bf(o1);
                *(uint32_t*)(Chi + p0) = (uint32_t)he0 | ((uint32_t)ho0 << 16);
                *(uint32_t*)(Chi + p1) = (uint32_t)he1 | ((uint32_t)ho1 << 16);
                unsigned short le0 = f2bf(e0 - bf2f(he0)), lo0 = f2bf(o0 - bf2f(ho0));
                unsigned short le1 = f2bf(e1 - bf2f(he1)), lo1 = f2bf(o1 - bf2f(ho1));
                *(uint32_t*)(Clo + p0) = (uint32_t)le0 | ((uint32_t)lo0 << 16);
                *(uint32_t*)(Clo + p1) = (uint32_t)le1 | ((uint32_t)lo1 << 16);
            }
        }
    }
}

__global__ __launch_bounds__(256, 2) void mm_qkv() {
    extern __shared__ char smm[];
    const int z = blockIdx.z;
    const unsigned short* Bhi = g_Wthi + (size_t)z * DM * DM;
    const unsigned short* Blo = g_Wtlo + (size_t)z * DM * DM;
    unsigned short* Chi = (z == 0) ? g_Qhi : (z == 1) ? g_Khi : g_Vhi;
    unsigned short* Clo = (z == 0) ? g_Qlo : (z == 1) ? g_Klo : g_Vlo;
    mm_body(smem_u32(smm), smm, g_Xhi, g_Xlo, Bhi, Blo, nullptr, Chi, Clo,
            (z < 2) ? 1 : 0, blockIdx.y * 64, blockIdx.x * 128);
}

__global__ __launch_bounds__(256, 2) void mm_out(float* __restrict__ Out) {
    extern __shared__ char smm[];
    mm_body(smem_u32(smm), smm, g_Yhi, g_Ylo, g_Wthi + (size_t)3 * DM * DM,
            g_Wtlo + (size_t)3 * DM * DM, Out, nullptr, nullptr, 0,
            blockIdx.y * 64, blockIdx.x * 128);
}

// ---------------- V chunk partials (from bf16 hi/lo) + suffix ----------------
__global__ __launch_bounds__(256) void v_partial() {
    int j = blockIdx.x;
    int c = blockIdx.y * 256 + threadIdx.x;
    const unsigned short* bh = g_Vhi + (size_t)(j * 32) * DM + c;
    const unsigned short* bl = g_Vlo + (size_t)(j * 32) * DM + c;
    float s = 0.f;
#pragma unroll
    for (int r = 0; r < 32; r++)
        s += bf2f(bh[(size_t)r * DM]) + bf2f(bl[(size_t)r * DM]);
    g_part[(size_t)j * DM + c] = s;
}
__global__ __launch_bounds__(256) void v_suffix2() {
    int j = blockIdx.x;
    int c = blockIdx.y * 256 + threadIdx.x;
    float s = 0.f;
    for (int i = j; i < 64; i++) s += g_part[(size_t)i * DM + c];
    g_Vsuf[(size_t)j * DM + c] = s;
}

// ---------------- Scores: paired-K ldmatrix.x4, pipelined head loop ----------
#define S_STRIDE 66
#define S_HEAD (32 * S_STRIDE)
#define SC_QH 0
#define SC_QL 4608
#define SC_KH 9216
#define SC_KL 18432
#define SC_STG 27648
#define SC_SBASE 135168
#define SMEM_SC (SC_SBASE + 2 * SC_STG)  // 190464

__global__ __launch_bounds__(256) void attn_sc() {
    extern __shared__ char sms[];
    float* S = (float*)sms;
    const uint32_t smb = smem_u32(sms);

    const int k0 = blockIdx.x * 64;
    const int q0 = (gridDim.y - 1 - blockIdx.y) * 32;  // big-work-first
    if (k0 >= (q0 & ~63) + 64) return;

    const int tid = threadIdx.x;
    const int wid = tid >> 5, lid = tid & 31;
    const int wm = wid & 1, wn = wid >> 1;
    const int trow = lid >> 2, quad = lid & 3;

    const uint32_t qOff = (uint32_t)(wm * 16 * 144 + (lid & 15) * 144 + (lid >> 4) * 16);
    // paired-K lane map: lane groups cover rows nf*8 of both fragments
    const uint32_t kOff = (uint32_t)((wn * 16 + ((lid >> 4) << 3) + (lid & 7)) * 144 +
                                     (((lid >> 3) & 1) << 4));

#define SC_ISSUE(hh, stg) do {                                                          \
        uint32_t sb = smb + SC_SBASE + (stg)*SC_STG;                                    \
        _Pragma("unroll")                                                               \
        for (int c2 = 0; c2 < 2; c2++) {                                                \
            int c = tid + c2 * 256;                                                     \
            int arr = c >> 8, r = (c & 255) >> 3, ch = c & 7;                           \
            const unsigned short* src = arr ? g_Qlo : g_Qhi;                            \
            cp16(sb + (arr ? SC_QL : SC_QH) + r * 144 + ch * 16,                        \
                 src + (size_t)(q0 + r) * DM + (hh)*HD + ch * 8);                       \
        }                                                                               \
        _Pragma("unroll")                                                               \
        for (int c2 = 0; c2 < 4; c2++) {                                                \
            int c = tid + c2 * 256;                                                     \
            int arr = c >> 9, r = (c & 511) >> 3, ch = c & 7;                           \
            const unsigned short* src = arr ? g_Klo : g_Khi;                            \
            cp16(sb + (arr ? SC_KL : SC_KH) + r * 144 + ch * 16,                        \
                 src + (size_t)(k0 + r) * DM + (hh)*HD + ch * 8);                       \
        }                                                                               \
        CP_COMMIT();                                                                    \
    } while (0)

    SC_ISSUE(0, 0);

    for (int h = 0; h < NH; h++) {
        if (h + 1 < NH) {
            SC_ISSUE(h + 1, (h + 1) & 1);
            CP_WAIT(1);
        } else {
            CP_WAIT(0);
        }
        __syncthreads();

        const uint32_t st = smb + SC_SBASE + (h & 1) * SC_STG;
        const uint32_t baseQh = st + SC_QH + qOff;
        const uint32_t baseQl = st + SC_QL + qOff;
        const uint32_t baseKh = st + SC_KH + kOff;
        const uint32_t baseKl = st + SC_KL + kOff;

        float acc[2][4] = {};
#pragma unroll
        for (int ks = 0; ks < 4; ks++) {
            uint32_t qh0, qh1, qh2, qh3, ql0, ql1, ql2, ql3;
            uint32_t kh0, kh1, kh2, kh3, kl0, kl1, kl2, kl3;
            ldmx4(baseQh + ks * 32, qh0, qh1, qh2, qh3);
            ldmx4(baseQl + ks * 32, ql0, ql1, ql2, ql3);
            ldmx4(baseKh + ks * 32, kh0, kh1, kh2, kh3);  // nf0: kh0,kh1; nf1: kh2,kh3
            ldmx4(baseKl + ks * 32, kl0, kl1, kl2, kl3);
            mma_bf16(acc[0], qh0, qh1, qh2, qh3, kh0, kh1);
            mma_bf16(acc[0], qh0, qh1, qh2, qh3, kl0, kl1);
            mma_bf16(acc[0], ql0, ql1, ql2, ql3, kh0, kh1);
            mma_bf16(acc[1], qh0, qh1, qh2, qh3, kh2, kh3);
            mma_bf16(acc[1], qh0, qh1, qh2, qh3, kl2, kl3);
            mma_bf16(acc[1], ql0, ql1, ql2, ql3, kh2, kh3);
        }
        float* Sh = S + h * S_HEAD;
#pragma unroll
        for (int nf = 0; nf < 2; nf++) {
            int row = wm * 16 + trow, col = wn * 16 + nf * 8 + quad * 2;
            Sh[row * S_STRIDE + col] = acc[nf][0] * 0.125f;
            Sh[row * S_STRIDE + col + 1] = acc[nf][1] * 0.125f;
            Sh[(row + 8) * S_STRIDE + col] = acc[nf][2] * 0.125f;
            Sh[(row + 8) * S_STRIDE + col + 1] = acc[nf][3] * 0.125f;
        }
        __syncthreads();
    }

    // Head-axis softmax per (q,k) cell
#pragma unroll
    for (int it = 0; it < 8; it++) {
        int idx = tid + it * 256;
        int row = idx >> 6, col = idx & 63;
        int q = q0 + row, k = k0 + col;
        float* cell = S + row * S_STRIDE + col;
        if (k > q) {
#pragma unroll
            for (int h = 0; h < NH; h++) cell[h * S_HEAD] = 0.0625f;
        } else {
            float e[NH], mx = -1e30f;
#pragma unroll
            for (int h = 0; h < NH; h++) {
                e[h] = cell[h * S_HEAD];
                mx = fmaxf(mx, e[h]);
            }
            float sum = 0.f;
#pragma unroll
            for (int h = 0; h < NH; h++) {
                e[h] = __expf(e[h] - mx);
                sum += e[h];
            }
            float inv = 1.0f / sum;
#pragma unroll
            for (int h = 0; h < NH; h++) cell[h * S_HEAD] = e[h] * inv;
        }
    }
    __syncthreads();

    // Writeback A as bf16 hi/lo pairs (STG.64: 4 columns per thread)
    for (int it = 0; it < 32; it++) {
        int idx = tid + it * 256;
        int h = idx >> 9;
        int rem = idx & 511;
        int row = rem >> 4, colq = (rem & 15) * 4;
        const float* cell = S + h * S_HEAD + row * S_STRIDE + colq;
        float a0 = cell[0], a1 = cell[1], a2 = cell[2], a3 = cell[3];
        unsigned short h0 = f2bf(a0), h1 = f2bf(a1), h2 = f2bf(a2), h3 = f2bf(a3);
        unsigned short l0 = f2bf(a0 - bf2f(h0)), l1 = f2bf(a1 - bf2f(h1));
        unsigned short l2 = f2bf(a2 - bf2f(h2)), l3 = f2bf(a3 - bf2f(h3));
        size_t p = ((size_t)h << 22) + (size_t)(q0 + row) * L + k0 + colq;
        *(uint2*)(g_Aah + p) = make_uint2((uint32_t)h0 | ((uint32_t)h1 << 16),
                                          (uint32_t)h2 | ((uint32_t)h3 << 16));
        *(uint2*)(g_Aal + p) = make_uint2((uint32_t)l0 | ((uint32_t)l1 << 16),
                                          (uint32_t)l2 | ((uint32_t)l3 << 16));
    }
}

// ---------------- AV: 2-stage cp.async pipeline -------------------------------
#define AV_A 0
#define AV_VH 8192
#define AV_VL 12288
#define AV_STG 16384
#define AV_SMEM (2 * AV_STG)  // 32768

__global__ __launch_bounds__(256) void attn_av() {
    extern __shared__ char sma[];
    const uint32_t smb = smem_u32(sma);

    const int q0 = (gridDim.x - 1 - blockIdx.x) * 64;  // big-work-first
    const int h = blockIdx.y;
    const int tid = threadIdx.x;
    const int wid = tid >> 5, lid = tid & 31;
    const int wm = wid & 1, wn = wid >> 1;
    const int klim = q0 + 64, nIter = klim >> 5;

    float acc[2][2][4] = {};

    const uint32_t xorv = (uint32_t)((lid & 7) << 4);
    const uint32_t aRow = (uint32_t)((wm * 32 + (lid & 15)) * 128);
    const uint32_t aChBase = (uint32_t)((lid >> 4) << 4);
    const uint32_t vRow = (uint32_t)(((lid & 7) + 8 * ((lid >> 3) & 1)) * 128);
    const uint32_t vCh = (uint32_t)(wn * 32 + ((lid >> 4) << 4)) ^ xorv;

#define AV_ISSUE(k0c, stg) do {                                                          \
        uint32_t sb = smb + (stg)*AV_STG;                                                \
        _Pragma("unroll")                                                                \
        for (int c2 = 0; c2 < 2; c2++) {                                                 \
            int c = tid + c2 * 256;                                                      \
            int r = c >> 3, ch = c & 7;                                                  \
            const unsigned short* src =                                                  \
                (ch < 4) ? (g_Aah + ((size_t)h << 22) + (size_t)(q0 + r) * L + (k0c) + ch * 8) \
                         : (g_Aal + ((size_t)h << 22) + (size_t)(q0 + r) * L + (k0c) + (ch - 4) * 8); \
            cp16(sb + AV_A + r * 128 + ((ch * 16) ^ ((r & 7) << 4)), src);               \
        }                                                                                \
        _Pragma("unroll")                                                                \
        for (int c2 = 0; c2 < 2; c2++) {                                                 \
            int c = tid + c2 * 256;                                                      \
            int arr = c >> 8, r = (c & 255) >> 3, ch = c & 7;                            \
            const unsigned short* src = arr ? g_Vlo : g_Vhi;                             \
            cp16(sb + (arr ? AV_VL : AV_VH) + r * 128 + ((ch * 16) ^ ((r & 7) << 4)),    \
                 src + (size_t)((k0c) + r) * DM + h * HD + ch * 8);                      \
        }                                                                                \
        CP_COMMIT();                                                                     \
    } while (0)

    AV_ISSUE(0, 0);

    for (int it = 0; it < nIter; it++) {
        if (it + 1 < nIter) {
            AV_ISSUE((it + 1) * 32, (it + 1) & 1);
            CP_WAIT(1);
        } else {
            CP_WAIT(0);
        }
        __syncthreads();

        const uint32_t st = smb + (it & 1) * AV_STG;
        const uint32_t baseA = st + AV_A + aRow;
        const uint32_t baseVh = st + AV_VH + vRow + vCh;
        const uint32_t baseVl = st + AV_VL + vRow + vCh;

#pragma unroll
        for (int ks = 0; ks < 2; ks++) {
            const uint32_t aChHi = (uint32_t)(ks * 32 + aChBase) ^ xorv;
            const uint32_t aChLo = (uint32_t)(64 + ks * 32 + aChBase) ^ xorv;
            uint32_t vh0, vh1, vh2, vh3, vl0, vl1, vl2, vl3;
            ldmx4t(baseVh + ks * 2048, vh0, vh1, vh2, vh3);
            ldmx4t(baseVl + ks * 2048, vl0, vl1, vl2, vl3);
#pragma unroll
            for (int mf = 0; mf < 2; mf++) {
                uint32_t ah0, ah1, ah2, ah3, al0, al1, al2, al3;
                ldmx4(baseA + mf * 2048 + aChHi, ah0, ah1, ah2, ah3);
                ldmx4(baseA + mf * 2048 + aChLo, al0, al1, al2, al3);
                mma_bf16(acc[mf][0], ah0, ah1, ah2, ah3, vh0, vh1);
                mma_bf16(acc[mf][0], ah0, ah1, ah2, ah3, vl0, vl1);
                mma_bf16(acc[mf][0], al0, al1, al2, al3, vh0, vh1);
                mma_bf16(acc[mf][1], ah0, ah1, ah2, ah3, vh2, vh3);
                mma_bf16(acc[mf][1], ah0, ah1, ah2, ah3, vl2, vl3);
                mma_bf16(acc[mf][1], al0, al1, al2, al3, vh2, vh3);
            }
        }
        __syncthreads();
    }

    const int trow = lid >> 2, quad = lid & 3;
#pragma unroll
    for (int nf = 0; nf < 2; nf++) {
        int dc = wn * 16 + nf * 8 + quad * 2;
        float s0 = 0.f, s1 = 0.f;
        if (klim < L) {
            const float* sb = g_Vsuf + (size_t)(klim >> 5) * DM + h * HD;
            s0 = sb[dc] * 0.0625f;
            s1 = sb[dc + 1] * 0.0625f;
        }
#pragma unroll
        for (int mf = 0; mf < 2; mf++) {
            int m = q0 + wm * 32 + mf * 16 + trow;
            float y00 = acc[mf][nf][0] + s0, y01 = acc[mf][nf][1] + s1;
            float y10 = acc[mf][nf][2] + s0, y11 = acc[mf][nf][3] + s1;
            size_t p0 = (size_t)m * DM + h * HD + dc;
            size_t p1 = (size_t)(m + 8) * DM + h * HD + dc;
            unsigned short h00 = f2bf(y00), h01 = f2bf(y01);
            unsigned short h10 = f2bf(y10), h11 = f2bf(y11);
            *(uint32_t*)(g_Yhi + p0) = (uint32_t)h00 | ((uint32_t)h01 << 16);
            *(uint32_t*)(g_Yhi + p1) = (uint32_t)h10 | ((uint32_t)h11 << 16);
            unsigned short l00 = f2bf(y00 - bf2f(h00)), l01 = f2bf(y01 - bf2f(h01));
            unsigned short l10 = f2bf(y10 - bf2f(h10)), l11 = f2bf(y11 - bf2f(h11));
            *(uint32_t*)(g_Ylo + p0) = (uint32_t)l00 | ((uint32_t)l01 << 16);
            *(uint32_t*)(g_Ylo + p1) = (uint32_t)l10 | ((uint32_t)l11 << 16);
        }
    }
}

// ---------------------------------------------------------------------------
extern "C" void kernel_launch(void* const* d_in, const int* in_sizes, int n_in,
                              void* d_out, int out_size) {
    const float* X = (const float*)d_in[0];
    const float* Wq = (const float*)d_in[2];
    const float* Wk = (const float*)d_in[3];
    const float* Wv = (const float*)d_in[4];
    const float* Wo = (const float*)d_in[5];
    float* Out = (float*)d_out;

    unsigned short *Xhi, *Xlo;
    cudaGetSymbolAddress((void**)&Xhi, g_Xhi);
    cudaGetSymbolAddress((void**)&Xlo, g_Xlo);

    cudaFuncSetAttribute(attn_sc, cudaFuncAttributeMaxDynamicSharedMemorySize, SMEM_SC);
    cudaFuncSetAttribute(mm_qkv, cudaFuncAttributeMaxDynamicSharedMemorySize, MM_SMEM);
    cudaFuncSetAttribute(mm_out, cudaFuncAttributeMaxDynamicSharedMemorySize, MM_SMEM);

    static cudaStream_t s2 = nullptr;
    static cudaEvent_t evF1, evJ1, evF2, evJ2;
    if (!s2) {
        cudaStreamCreateWithFlags(&s2, cudaStreamNonBlocking);
        cudaEventCreateWithFlags(&evF1, cudaEventDisableTiming);
        cudaEventCreateWithFlags(&evJ1, cudaEventDisableTiming);
        cudaEventCreateWithFlags(&evF2, cudaEventDisableTiming);
        cudaEventCreateWithFlags(&evJ2, cudaEventDisableTiming);
    }

    // Fork 1: wsplit4 (weights) on s2 overlapped with xsplit (X) on main
    cudaEventRecord(evF1, 0);
    cudaStreamWaitEvent(s2, evF1, 0);
    wsplit4<<<dim3(DM / 32, DM / 32, 4), 256, 0, s2>>>(Wq, Wk, Wv, Wo);
    xsplit<<<(L * DM) / 1024, 256>>>(X, Xhi, Xlo);
    cudaEventRecord(evJ1, s2);
    cudaStreamWaitEvent(0, evJ1, 0);

    mm_qkv<<<dim3(DM / 128, L / 64, 3), 256, MM_SMEM>>>();

    // Fork 2: V suffix chain on s2 overlapped with attn_sc on main
    cudaEventRecord(evF2, 0);
    cudaStreamWaitEvent(s2, evF2, 0);
    v_partial<<<dim3(64, 4), 256, 0, s2>>>();
    v_suffix2<<<dim3(64, 4), 256, 0, s2>>>();
    cudaEventRecord(evJ2, s2);
    attn_sc<<<dim3(L / 64, L / 32), 256, SMEM_SC>>>();
    cudaStreamWaitEvent(0, evJ2, 0);

    attn_av<<<dim3(L / 64, NH), 256, AV_SMEM>>>();

    mm_out<<<dim3(DM / 128, L / 64), 256, MM_SMEM>>>(Out);
}

// round 17
// speedup vs baseline: 1.0417x; 1.0417x over previous
#include <cuda_runtime.h>
#include <cuda_bf16.h>
#include <math.h>
#include <stdint.h>

#define L 2048
#define DM 1024
#define NH 16
#define HD 64

// ---------------- Scratch (device globals — no allocation allowed) ----------
__device__ __align__(16) float g_part[64 * DM];
__device__ __align__(16) float g_Vsuf[64 * DM];
__device__ __align__(16) float g_rope[L * 64];              // [m][t]: cos at t, sin at t+1 (t even)
__device__ __align__(16) unsigned short g_Aah[(size_t)NH * L * L];  // A bf16 hi
__device__ __align__(16) unsigned short g_Aal[(size_t)NH * L * L];  // A bf16 lo
__device__ __align__(16) unsigned short g_Xhi[L * DM];
__device__ __align__(16) unsigned short g_Xlo[L * DM];
__device__ __align__(16) unsigned short g_Yhi[L * DM];
__device__ __align__(16) unsigned short g_Ylo[L * DM];
__device__ __align__(16) unsigned short g_Qhi[L * DM];
__device__ __align__(16) unsigned short g_Qlo[L * DM];
__device__ __align__(16) unsigned short g_Khi[L * DM];
__device__ __align__(16) unsigned short g_Klo[L * DM];
__device__ __align__(16) unsigned short g_Vhi[L * DM];
__device__ __align__(16) unsigned short g_Vlo[L * DM];
__device__ __align__(16) unsigned short g_Wthi[4 * DM * DM];  // W^T [n][k]
__device__ __align__(16) unsigned short g_Wtlo[4 * DM * DM];

// -log2(500)/64
#define ROPE_LOG2C 0.14009037944784838

__device__ __forceinline__ uint32_t smem_u32(const void* p) {
    uint32_t a;
    asm("{ .reg .u64 t; cvta.to.shared.u64 t, %1; cvt.u32.u64 %0, t; }" : "=r"(a) : "l"(p));
    return a;
}
__device__ __forceinline__ void cp16(uint32_t saddr, const void* gaddr) {
    asm volatile("cp.async.cg.shared.global [%0], [%1], 16;" :: "r"(saddr), "l"(gaddr));
}
#define CP_COMMIT() asm volatile("cp.async.commit_group;" ::: "memory")
#define CP_WAIT(n) asm volatile("cp.async.wait_group %0;" :: "n"(n) : "memory")

__device__ __forceinline__ void ldmx4(uint32_t addr, uint32_t& r0, uint32_t& r1,
                                      uint32_t& r2, uint32_t& r3) {
    asm volatile("ldmatrix.sync.aligned.m8n8.x4.shared.b16 {%0,%1,%2,%3}, [%4];"
                 : "=r"(r0), "=r"(r1), "=r"(r2), "=r"(r3) : "r"(addr));
}
__device__ __forceinline__ void ldmx4t(uint32_t addr, uint32_t& r0, uint32_t& r1,
                                       uint32_t& r2, uint32_t& r3) {
    asm volatile("ldmatrix.sync.aligned.m8n8.x4.trans.shared.b16 {%0,%1,%2,%3}, [%4];"
                 : "=r"(r0), "=r"(r1), "=r"(r2), "=r"(r3) : "r"(addr));
}
__device__ __forceinline__ void ldmx2(uint32_t addr, uint32_t& r0, uint32_t& r1) {
    asm volatile("ldmatrix.sync.aligned.m8n8.x2.shared.b16 {%0,%1}, [%2];"
                 : "=r"(r0), "=r"(r1) : "r"(addr));
}
__device__ __forceinline__ void mma_bf16(float* c, uint32_t a0, uint32_t a1, uint32_t a2,
                                         uint32_t a3, uint32_t b0, uint32_t b1) {
    asm volatile(
        "mma.sync.aligned.m16n8k16.row.col.f32.bf16.bf16.f32 "
        "{%0,%1,%2,%3}, {%4,%5,%6,%7}, {%8,%9}, {%0,%1,%2,%3};"
        : "+f"(c[0]), "+f"(c[1]), "+f"(c[2]), "+f"(c[3])
        : "r"(a0), "r"(a1), "r"(a2), "r"(a3), "r"(b0), "r"(b1));
}

__device__ __forceinline__ unsigned short f2bf(float v) {
    __nv_bfloat16 b = __float2bfloat16(v);
    return *(unsigned short*)&b;
}
__device__ __forceinline__ float bf2f(unsigned short u) {
    __nv_bfloat16 b = *(__nv_bfloat16*)&u;
    return __bfloat162float(b);
}

// ---------------- Prep kernels ----------------------------------------------
__global__ __launch_bounds__(256) void xsplit(const float* __restrict__ X,
                                              unsigned short* __restrict__ hi,
                                              unsigned short* __restrict__ lo) {
    size_t i = ((size_t)blockIdx.x * 256 + threadIdx.x) * 4;
    float4 v = *(const float4*)(X + i);
    unsigned short h0 = f2bf(v.x), h1 = f2bf(v.y), h2 = f2bf(v.z), h3 = f2bf(v.w);
    unsigned short l0 = f2bf(v.x - bf2f(h0)), l1 = f2bf(v.y - bf2f(h1));
    unsigned short l2 = f2bf(v.z - bf2f(h2)), l3 = f2bf(v.w - bf2f(h3));
    *(uint2*)(hi + i) = make_uint2((uint32_t)h0 | ((uint32_t)h1 << 16),
                                   (uint32_t)h2 | ((uint32_t)h3 << 16));
    *(uint2*)(lo + i) = make_uint2((uint32_t)l0 | ((uint32_t)l1 << 16),
                                   (uint32_t)l2 | ((uint32_t)l3 << 16));
}

__global__ __launch_bounds__(256) void wsplit4(const float* __restrict__ W0,
                                               const float* __restrict__ W1,
                                               const float* __restrict__ W2,
                                               const float* __restrict__ W3) {
    __shared__ float s[32][33];
    const int z = blockIdx.z;
    const float* W = (z == 0) ? W0 : (z == 1) ? W1 : (z == 2) ? W2 : W3;
    unsigned short* hi = g_Wthi + (size_t)z * DM * DM;
    unsigned short* lo = g_Wtlo + (size_t)z * DM * DM;
    int n0 = blockIdx.x * 32, k0 = blockIdx.y * 32;
    int tx = threadIdx.x & 31, ty = threadIdx.x >> 5;
#pragma unroll
    for (int d = 0; d < 4; d++) {
        int i = ty * 4 + d;
        s[i][tx] = W[(size_t)(k0 + i) * DM + n0 + tx];
    }
    __syncthreads();
#pragma unroll
    for (int d = 0; d < 4; d++) {
        int i = ty * 4 + d;
        float v = s[tx][i];
        unsigned short h = f2bf(v);
        unsigned short l = f2bf(v - bf2f(h));
        hi[(size_t)(n0 + i) * DM + k0 + tx] = h;
        lo[(size_t)(n0 + i) * DM + k0 + tx] = l;
    }
}

// RoPE table: exact same float ops as the old epilogue -> bit-identical coeffs
__global__ __launch_bounds__(256) void ropetab() {
    int idx = blockIdx.x * 256 + threadIdx.x;  // 0..65535
    int m = idx >> 5, tt = idx & 31;
    int t = tt * 2;
    float fr = (float)exp2(-(double)t * ROPE_LOG2C);
    float s, c;
    sincosf((float)m * fr, &s, &c);
    *(float2*)(g_rope + (size_t)m * 64 + t) = make_float2(c, s);
}

// ---------------- HMMA GEMM body (R15 layout, table-based RoPE) --------------
#define OF_AH 0
#define OF_AL 8192
#define OF_BH 16384
#define OF_BL 32768
#define STG 49152
#define MM_SMEM (2 * STG)

__device__ __forceinline__ void mm_body(uint32_t smb, char* smm,
                                        const unsigned short* __restrict__ Ahi,
                                        const unsigned short* __restrict__ Alo,
                                        const unsigned short* __restrict__ Bhi,
                                        const unsigned short* __restrict__ Blo,
                                        float* __restrict__ Cf,
                                        unsigned short* __restrict__ Chi,
                                        unsigned short* __restrict__ Clo,
                                        int doRope, int m0, int n0) {
    const int tid = threadIdx.x;
    const int wid = tid >> 5, lid = tid & 31;
    const int wm = wid & 1, wn = wid >> 1;

    float acc[2][4][4] = {};

    const int lrow0 = tid >> 3, lch = tid & 7;
    const uint32_t lsw0 = (uint32_t)(lrow0 * 128 + ((lch * 16) ^ ((lrow0 & 7) << 4)));
    const uint32_t xorv = (uint32_t)((lid & 7) << 4);
    const uint32_t aRow = (uint32_t)((wm * 32 + (lid & 15)) * 128);
    const uint32_t bRow = (uint32_t)((wn * 32 + (lid & 7)) * 128);
    const uint32_t aChBase = (uint32_t)((lid >> 4) << 4);
    const uint32_t bChBase = (uint32_t)(((lid >> 3) & 1) << 4);

#define LOAD_STAGE(k0c, stg) do {                                                  \
        uint32_t sb = smb + (stg)*STG;                                             \
        _Pragma("unroll")                                                          \
        for (int it = 0; it < 2; it++) {                                           \
            int row = lrow0 + it * 32;                                             \
            uint32_t so = lsw0 + it * 4096;                                        \
            size_t ga = (size_t)(m0 + row) * DM + (k0c) + lch * 8;                 \
            cp16(sb + OF_AH + so, Ahi + ga);                                       \
            cp16(sb + OF_AL + so, Alo + ga);                                       \
        }                                                                          \
        _Pragma("unroll")                                                          \
        for (int it = 0; it < 4; it++) {                                           \
            int row = lrow0 + it * 32;                                             \
            uint32_t so = lsw0 + it * 4096;                                        \
            size_t gb = (size_t)(n0 + row) * DM + (k0c) + lch * 8;                 \
            cp16(sb + OF_BH + so, Bhi + gb);                                       \
            cp16(sb + OF_BL + so, Blo + gb);                                       \
        }                                                                          \
        CP_COMMIT();                                                               \
    } while (0)

    LOAD_STAGE(0, 0);

    for (int c = 0; c < 16; c++) {
        if (c + 1 < 16) {
            LOAD_STAGE((c + 1) * 64, (c + 1) & 1);
            CP_WAIT(1);
        } else {
            CP_WAIT(0);
        }
        __syncthreads();

        const uint32_t st = smb + (c & 1) * STG;
        const uint32_t baseAh = st + OF_AH + aRow;
        const uint32_t baseAl = st + OF_AL + aRow;
        const uint32_t baseBh = st + OF_BH + bRow;
        const uint32_t baseBl = st + OF_BL + bRow;

#pragma unroll
        for (int ks = 0; ks < 4; ks++) {
            const uint32_t aCh = (uint32_t)(ks * 32 + aChBase) ^ xorv;
            const uint32_t bCh = (uint32_t)(ks * 32 + bChBase) ^ xorv;
            uint32_t bh[4][2], bl[4][2];
#pragma unroll
            for (int j = 0; j < 4; j++) {
                ldmx2(baseBh + j * 1024 + bCh, bh[j][0], bh[j][1]);
                ldmx2(baseBl + j * 1024 + bCh, bl[j][0], bl[j][1]);
            }
#pragma unroll
            for (int i = 0; i < 2; i++) {
                uint32_t ah0, ah1, ah2, ah3, al0, al1, al2, al3;
                ldmx4(baseAh + i * 2048 + aCh, ah0, ah1, ah2, ah3);
                ldmx4(baseAl + i * 2048 + aCh, al0, al1, al2, al3);
#pragma unroll
                for (int j = 0; j < 4; j++) {
                    mma_bf16(acc[i][j], ah0, ah1, ah2, ah3, bh[j][0], bh[j][1]);
                    mma_bf16(acc[i][j], ah0, ah1, ah2, ah3, bl[j][0], bl[j][1]);
                    mma_bf16(acc[i][j], al0, al1, al2, al3, bh[j][0], bh[j][1]);
                }
            }
        }
        __syncthreads();
    }

    const int quad = lid & 3, trow = lid >> 2;
#pragma unroll
    for (int i = 0; i < 2; i++) {
        int mA = m0 + wm * 32 + i * 16 + trow;
#pragma unroll
        for (int j = 0; j < 4; j++) {
            int n = n0 + wn * 32 + j * 8 + quad * 2;
            float e0 = acc[i][j][0], o0 = acc[i][j][1];
            float e1 = acc[i][j][2], o1 = acc[i][j][3];
            if (doRope) {
                int t = n & 63;
                float2 cs0 = *(const float2*)(g_rope + (size_t)mA * 64 + t);
                float te = e0;
                e0 = te * cs0.x - o0 * cs0.y;
                o0 = te * cs0.y + o0 * cs0.x;
                float2 cs1 = *(const float2*)(g_rope + (size_t)(mA + 8) * 64 + t);
                te = e1;
                e1 = te * cs1.x - o1 * cs1.y;
                o1 = te * cs1.y + o1 * cs1.x;
            }
            size_t p0 = (size_t)mA * DM + n, p1 = (size_t)(mA + 8) * DM + n;
            if (Cf) {
                *(float2*)(Cf + p0) = make_float2(e0, o0);
                *(float2*)(Cf + p1) = make_float2(e1, o1);
            }
            if (Chi) {
                unsigned short he0 = f2bf(e0), ho0 = f2bf(o0);
                unsigned short he1 = f2bf(e1), ho1 = f2bf(o1);
                *(uint32_t*)(Chi + p0) = (uint32_t)he0 | ((uint32_t)ho0 << 16);
                *(uint32_t*)(Chi + p1) = (uint32_t)he1 | ((uint32_t)ho1 << 16);
                unsigned short le0 = f2bf(e0 - bf2f(he0)), lo0 = f2bf(o0 - bf2f(ho0));
                unsigned short le1 = f2bf(e1 - bf2f(he1)), lo1 = f2bf(o1 - bf2f(ho1));
                *(uint32_t*)(Clo + p0) = (uint32_t)le0 | ((uint32_t)lo0 << 16);
                *(uint32_t*)(Clo + p1) = (uint32_t)le1 | ((uint32_t)lo1 << 16);
            }
        }
    }
}

__global__ __launch_bounds__(256, 2) void mm_qkv() {
    extern __shared__ char smm[];
    const int z = blockIdx.z;
    const unsigned short* Bhi = g_Wthi + (size_t)z * DM * DM;
    const unsigned short* Blo = g_Wtlo + (size_t)z * DM * DM;
    unsigned short* Chi = (z == 0) ? g_Qhi : (z == 1) ? g_Khi : g_Vhi;
    unsigned short* Clo = (z == 0) ? g_Qlo : (z == 1) ? g_Klo : g_Vlo;
    mm_body(smem_u32(smm), smm, g_Xhi, g_Xlo, Bhi, Blo, nullptr, Chi, Clo,
            (z < 2) ? 1 : 0, blockIdx.y * 64, blockIdx.x * 128);
}

__global__ __launch_bounds__(256, 2) void mm_out(float* __restrict__ Out) {
    extern __shared__ char smm[];
    mm_body(smem_u32(smm), smm, g_Yhi, g_Ylo, g_Wthi + (size_t)3 * DM * DM,
            g_Wtlo + (size_t)3 * DM * DM, Out, nullptr, nullptr, 0,
            blockIdx.y * 64, blockIdx.x * 128);
}

// ---------------- V chunk partials (from bf16 hi/lo) + suffix ----------------
__global__ __launch_bounds__(256) void v_partial() {
    int j = blockIdx.x;
    int c = blockIdx.y * 256 + threadIdx.x;
    const unsigned short* bh = g_Vhi + (size_t)(j * 32) * DM + c;
    const unsigned short* bl = g_Vlo + (size_t)(j * 32) * DM + c;
    float s = 0.f;
#pragma unroll
    for (int r = 0; r < 32; r++)
        s += bf2f(bh[(size_t)r * DM]) + bf2f(bl[(size_t)r * DM]);
    g_part[(size_t)j * DM + c] = s;
}
__global__ __launch_bounds__(256) void v_suffix2() {
    int j = blockIdx.x;
    int c = blockIdx.y * 256 + threadIdx.x;
    float s = 0.f;
    for (int i = j; i < 64; i++) s += g_part[(size_t)i * DM + c];
    g_Vsuf[(size_t)j * DM + c] = s;
}

// ---------------- Scores: 2-stage pipelined head loop (R15) ------------------
#define S_STRIDE 66
#define S_HEAD (32 * S_STRIDE)
#define SC_QH 0
#define SC_QL 4608
#define SC_KH 9216
#define SC_KL 18432
#define SC_STG 27648
#define SC_SBASE 135168
#define SMEM_SC (SC_SBASE + 2 * SC_STG)  // 190464

__global__ __launch_bounds__(256) void attn_sc() {
    extern __shared__ char sms[];
    float* S = (float*)sms;
    const uint32_t smb = smem_u32(sms);

    const int k0 = blockIdx.x * 64;
    const int q0 = (gridDim.y - 1 - blockIdx.y) * 32;  // big-work-first
    if (k0 >= (q0 & ~63) + 64) return;

    const int tid = threadIdx.x;
    const int wid = tid >> 5, lid = tid & 31;
    const int wm = wid & 1, wn = wid >> 1;
    const int trow = lid >> 2, quad = lid & 3;

    const uint32_t qOff = (uint32_t)(wm * 16 * 144 + (lid & 15) * 144 + (lid >> 4) * 16);
    const uint32_t kOff = (uint32_t)(wn * 16 * 144 + (lid & 7) * 144 + ((lid >> 3) & 1) * 16);

#define SC_ISSUE(hh, stg) do {                                                          \
        uint32_t sb = smb + SC_SBASE + (stg)*SC_STG;                                    \
        _Pragma("unroll")                                                               \
        for (int c2 = 0; c2 < 2; c2++) {                                                \
            int c = tid + c2 * 256;                                                     \
            int arr = c >> 8, r = (c & 255) >> 3, ch = c & 7;                           \
            const unsigned short* src = arr ? g_Qlo : g_Qhi;                            \
            cp16(sb + (arr ? SC_QL : SC_QH) + r * 144 + ch * 16,                        \
                 src + (size_t)(q0 + r) * DM + (hh)*HD + ch * 8);                       \
        }                                                                               \
        _Pragma("unroll")                                                               \
        for (int c2 = 0; c2 < 4; c2++) {                                                \
            int c = tid + c2 * 256;                                                     \
            int arr = c >> 9, r = (c & 511) >> 3, ch = c & 7;                           \
            const unsigned short* src = arr ? g_Klo : g_Khi;                            \
            cp16(sb + (arr ? SC_KL : SC_KH) + r * 144 + ch * 16,                        \
                 src + (size_t)(k0 + r) * DM + (hh)*HD + ch * 8);                       \
        }                                                                               \
        CP_COMMIT();                                                                    \
    } while (0)

    SC_ISSUE(0, 0);

    for (int h = 0; h < NH; h++) {
        if (h + 1 < NH) {
            SC_ISSUE(h + 1, (h + 1) & 1);
            CP_WAIT(1);
        } else {
            CP_WAIT(0);
        }
        __syncthreads();

        const uint32_t st = smb + SC_SBASE + (h & 1) * SC_STG;
        const uint32_t baseQh = st + SC_QH + qOff;
        const uint32_t baseQl = st + SC_QL + qOff;
        const uint32_t baseKh = st + SC_KH + kOff;
        const uint32_t baseKl = st + SC_KL + kOff;

        float acc[2][4] = {};
#pragma unroll
        for (int ks = 0; ks < 4; ks++) {
            uint32_t qh0, qh1, qh2, qh3, ql0, ql1, ql2, ql3;
            ldmx4(baseQh + ks * 32, qh0, qh1, qh2, qh3);
            ldmx4(baseQl + ks * 32, ql0, ql1, ql2, ql3);
#pragma unroll
            for (int nf = 0; nf < 2; nf++) {
                uint32_t kh0, kh1, kl0, kl1;
                ldmx2(baseKh + nf * 1152 + ks * 32, kh0, kh1);
                ldmx2(baseKl + nf * 1152 + ks * 32, kl0, kl1);
                mma_bf16(acc[nf], qh0, qh1, qh2, qh3, kh0, kh1);
                mma_bf16(acc[nf], qh0, qh1, qh2, qh3, kl0, kl1);
                mma_bf16(acc[nf], ql0, ql1, ql2, ql3, kh0, kh1);
            }
        }
        float* Sh = S + h * S_HEAD;
#pragma unroll
        for (int nf = 0; nf < 2; nf++) {
            int row = wm * 16 + trow, col = wn * 16 + nf * 8 + quad * 2;
            Sh[row * S_STRIDE + col] = acc[nf][0] * 0.125f;
            Sh[row * S_STRIDE + col + 1] = acc[nf][1] * 0.125f;
            Sh[(row + 8) * S_STRIDE + col] = acc[nf][2] * 0.125f;
            Sh[(row + 8) * S_STRIDE + col + 1] = acc[nf][3] * 0.125f;
        }
        __syncthreads();
    }

    // Head-axis softmax per (q,k) cell
#pragma unroll
    for (int it = 0; it < 8; it++) {
        int idx = tid + it * 256;
        int row = idx >> 6, col = idx & 63;
        int q = q0 + row, k = k0 + col;
        float* cell = S + row * S_STRIDE + col;
        if (k > q) {
#pragma unroll
            for (int h = 0; h < NH; h++) cell[h * S_HEAD] = 0.0625f;
        } else {
            float e[NH], mx = -1e30f;
#pragma unroll
            for (int h = 0; h < NH; h++) {
                e[h] = cell[h * S_HEAD];
                mx = fmaxf(mx, e[h]);
            }
            float sum = 0.f;
#pragma unroll
            for (int h = 0; h < NH; h++) {
                e[h] = __expf(e[h] - mx);
                sum += e[h];
            }
            float inv = 1.0f / sum;
#pragma unroll
            for (int h = 0; h < NH; h++) cell[h * S_HEAD] = e[h] * inv;
        }
    }
    __syncthreads();

    // Writeback A as bf16 hi/lo pairs
    for (int it = 0; it < 64; it++) {
        int idx = tid + it * 256;
        int h = idx >> 10;
        int rem = idx & 1023;
        int row = rem >> 5, colp = (rem & 31) * 2;
        const float* cell = S + h * S_HEAD + row * S_STRIDE + colp;
        float a0 = cell[0], a1 = cell[1];
        unsigned short h0 = f2bf(a0), h1 = f2bf(a1);
        unsigned short l0 = f2bf(a0 - bf2f(h0)), l1 = f2bf(a1 - bf2f(h1));
        size_t p = ((size_t)h << 22) + (size_t)(q0 + row) * L + k0 + colp;
        *(uint32_t*)(g_Aah + p) = (uint32_t)h0 | ((uint32_t)h1 << 16);
        *(uint32_t*)(g_Aal + p) = (uint32_t)l0 | ((uint32_t)l1 << 16);
    }
}

// ---------------- AV: 2-stage cp.async pipeline (R15) -------------------------
#define AV_A 0
#define AV_VH 8192
#define AV_VL 12288
#define AV_STG 16384
#define AV_SMEM (2 * AV_STG)  // 32768

__global__ __launch_bounds__(256) void attn_av() {
    extern __shared__ char sma[];
    const uint32_t smb = smem_u32(sma);

    const int q0 = (gridDim.x - 1 - blockIdx.x) * 64;  // big-work-first
    const int h = blockIdx.y;
    const int tid = threadIdx.x;
    const int wid = tid >> 5, lid = tid & 31;
    const int wm = wid & 1, wn = wid >> 1;
    const int klim = q0 + 64, nIter = klim >> 5;

    float acc[2][2][4] = {};

    const uint32_t xorv = (uint32_t)((lid & 7) << 4);
    const uint32_t aRow = (uint32_t)((wm * 32 + (lid & 15)) * 128);
    const uint32_t aChBase = (uint32_t)((lid >> 4) << 4);
    const uint32_t vRow = (uint32_t)(((lid & 7) + 8 * ((lid >> 3) & 1)) * 128);
    const uint32_t vCh = (uint32_t)(wn * 32 + ((lid >> 4) << 4)) ^ xorv;

#define AV_ISSUE(k0c, stg) do {                                                          \
        uint32_t sb = smb + (stg)*AV_STG;                                                \
        _Pragma("unroll")                                                                \
        for (int c2 = 0; c2 < 2; c2++) {                                                 \
            int c = tid + c2 * 256;                                                      \
            int r = c >> 3, ch = c & 7;                                                  \
            const unsigned short* src =                                                  \
                (ch < 4) ? (g_Aah + ((size_t)h << 22) + (size_t)(q0 + r) * L + (k0c) + ch * 8) \
                         : (g_Aal + ((size_t)h << 22) + (size_t)(q0 + r) * L + (k0c) + (ch - 4) * 8); \
            cp16(sb + AV_A + r * 128 + ((ch * 16) ^ ((r & 7) << 4)), src);               \
        }                                                                                \
        _Pragma("unroll")                                                                \
        for (int c2 = 0; c2 < 2; c2++) {                                                 \
            int c = tid + c2 * 256;                                                      \
            int arr = c >> 8, r = (c & 255) >> 3, ch = c & 7;                            \
            const unsigned short* src = arr ? g_Vlo : g_Vhi;                             \
            cp16(sb + (arr ? AV_VL : AV_VH) + r * 128 + ((ch * 16) ^ ((r & 7) << 4)),    \
                 src + (size_t)((k0c) + r) * DM + h * HD + ch * 8);                      \
        }                                                                                \
        CP_COMMIT();                                                                     \
    } while (0)

    AV_ISSUE(0, 0);

    for (int it = 0; it < nIter; it++) {
        if (it + 1 < nIter) {
            AV_ISSUE((it + 1) * 32, (it + 1) & 1);
            CP_WAIT(1);
        } else {
            CP_WAIT(0);
        }
        __syncthreads();

        const uint32_t st = smb + (it & 1) * AV_STG;
        const uint32_t baseA = st + AV_A + aRow;
        const uint32_t baseVh = st + AV_VH + vRow + vCh;
        const uint32_t baseVl = st + AV_VL + vRow + vCh;

#pragma unroll
        for (int ks = 0; ks < 2; ks++) {
            const uint32_t aChHi = (uint32_t)(ks * 32 + aChBase) ^ xorv;
            const uint32_t aChLo = (uint32_t)(64 + ks * 32 + aChBase) ^ xorv;
            uint32_t vh0, vh1, vh2, vh3, vl0, vl1, vl2, vl3;
            ldmx4t(baseVh + ks * 2048, vh0, vh1, vh2, vh3);
            ldmx4t(baseVl + ks * 2048, vl0, vl1, vl2, vl3);
#pragma unroll
            for (int mf = 0; mf < 2; mf++) {
                uint32_t ah0, ah1, ah2, ah3, al0, al1, al2, al3;
                ldmx4(baseA + mf * 2048 + aChHi, ah0, ah1, ah2, ah3);
                ldmx4(baseA + mf * 2048 + aChLo, al0, al1, al2, al3);
                mma_bf16(acc[mf][0], ah0, ah1, ah2, ah3, vh0, vh1);
                mma_bf16(acc[mf][0], ah0, ah1, ah2, ah3, vl0, vl1);
                mma_bf16(acc[mf][0], al0, al1, al2, al3, vh0, vh1);
                mma_bf16(acc[mf][1], ah0, ah1, ah2, ah3, vh2, vh3);
                mma_bf16(acc[mf][1], ah0, ah1, ah2, ah3, vl2, vl3);
                mma_bf16(acc[mf][1], al0, al1, al2, al3, vh2, vh3);
            }
        }
        __syncthreads();
    }

    const int trow = lid >> 2, quad = lid & 3;
#pragma unroll
    for (int nf = 0; nf < 2; nf++) {
        int dc = wn * 16 + nf * 8 + quad * 2;
        float s0 = 0.f, s1 = 0.f;
        if (klim < L) {
            const float* sb = g_Vsuf + (size_t)(klim >> 5) * DM + h * HD;
            s0 = sb[dc] * 0.0625f;
            s1 = sb[dc + 1] * 0.0625f;
        }
#pragma unroll
        for (int mf = 0; mf < 2; mf++) {
            int m = q0 + wm * 32 + mf * 16 + trow;
            float y00 = acc[mf][nf][0] + s0, y01 = acc[mf][nf][1] + s1;
            float y10 = acc[mf][nf][2] + s0, y11 = acc[mf][nf][3] + s1;
            size_t p0 = (size_t)m * DM + h * HD + dc;
            size_t p1 = (size_t)(m + 8) * DM + h * HD + dc;
            unsigned short h00 = f2bf(y00), h01 = f2bf(y01);
            unsigned short h10 = f2bf(y10), h11 = f2bf(y11);
            *(uint32_t*)(g_Yhi + p0) = (uint32_t)h00 | ((uint32_t)h01 << 16);
            *(uint32_t*)(g_Yhi + p1) = (uint32_t)h10 | ((uint32_t)h11 << 16);
            unsigned short l00 = f2bf(y00 - bf2f(h00)), l01 = f2bf(y01 - bf2f(h01));
            unsigned short l10 = f2bf(y10 - bf2f(h10)), l11 = f2bf(y11 - bf2f(h11));
            *(uint32_t*)(g_Ylo + p0) = (uint32_t)l00 | ((uint32_t)l01 << 16);
            *(uint32_t*)(g_Ylo + p1) = (uint32_t)l10 | ((uint32_t)l11 << 16);
        }
    }
}

// ---------------------------------------------------------------------------
extern "C" void kernel_launch(void* const* d_in, const int* in_sizes, int n_in,
                              void* d_out, int out_size) {
    const float* X = (const float*)d_in[0];
    const float* Wq = (const float*)d_in[2];
    const float* Wk = (const float*)d_in[3];
    const float* Wv = (const float*)d_in[4];
    const float* Wo = (const float*)d_in[5];
    float* Out = (float*)d_out;

    unsigned short *Xhi, *Xlo;
    cudaGetSymbolAddress((void**)&Xhi, g_Xhi);
    cudaGetSymbolAddress((void**)&Xlo, g_Xlo);

    cudaFuncSetAttribute(attn_sc, cudaFuncAttributeMaxDynamicSharedMemorySize, SMEM_SC);
    cudaFuncSetAttribute(mm_qkv, cudaFuncAttributeMaxDynamicSharedMemorySize, MM_SMEM);
    cudaFuncSetAttribute(mm_out, cudaFuncAttributeMaxDynamicSharedMemorySize, MM_SMEM);

    static cudaStream_t s2 = nullptr;
    static cudaEvent_t evF1, evJ1, evF2, evJ2;
    if (!s2) {
        cudaStreamCreateWithFlags(&s2, cudaStreamNonBlocking);
        cudaEventCreateWithFlags(&evF1, cudaEventDisableTiming);
        cudaEventCreateWithFlags(&evJ1, cudaEventDisableTiming);
        cudaEventCreateWithFlags(&evF2, cudaEventDisableTiming);
        cudaEventCreateWithFlags(&evJ2, cudaEventDisableTiming);
    }

    // Fork 1: wsplit4 + ropetab (weights/table) on s2 overlapped with xsplit
    cudaEventRecord(evF1, 0);
    cudaStreamWaitEvent(s2, evF1, 0);
    wsplit4<<<dim3(DM / 32, DM / 32, 4), 256, 0, s2>>>(Wq, Wk, Wv, Wo);
    ropetab<<<256, 256, 0, s2>>>();
    xsplit<<<(L * DM) / 1024, 256>>>(X, Xhi, Xlo);
    cudaEventRecord(evJ1, s2);
    cudaStreamWaitEvent(0, evJ1, 0);

    mm_qkv<<<dim3(DM / 128, L / 64, 3), 256, MM_SMEM>>>();

    // Fork 2: V suffix chain on s2 overlapped with attn_sc on main
    cudaEventRecord(evF2, 0);
    cudaStreamWaitEvent(s2, evF2, 0);
    v_partial<<<dim3(64, 4), 256, 0, s2>>>();
    v_suffix2<<<dim3(64, 4), 256, 0, s2>>>();
    cudaEventRecord(evJ2, s2);
    attn_sc<<<dim3(L / 64, L / 32), 256, SMEM_SC>>>();
    cudaStreamWaitEvent(0, evJ2, 0);

    attn_av<<<dim3(L / 64, NH), 256, AV_SMEM>>>();

    mm_out<<<dim3(DM / 128, L / 64), 256, MM_SMEM>>>(Out);
}